// round 11
// baseline (speedup 1.0000x reference)
#include <cuda_runtime.h>
#include <math_constants.h>

// ChamferLoss bidirectional, single pass over the 16384x16384 d2 matrix.
// d2 = (|y|^2 - 2 x.y) + |x|^2 via packed fma.rn.f32x2 (2 gt cols per op).
// Row/col mins merged globally via REDG atomicMax on ~bits(d2): for positive
// floats bit-pattern order == value order, so max(~bits) == min(value);
// key=0 is the identity, so zero-initialized keys need no init pass, and the
// reduce kernel resets them to 0 for graph-replay determinism.

#define NPTS        16384
#define NROWG       256          // row groups (64 pred rows each)
#define NCOLG       8            // col groups (2048 gt cols each)
#define ROWS_PB     64
#define COLS_PT     8
#define THREADS     256

typedef unsigned long long ull;
typedef unsigned int uint32;

__device__ uint32 g_rowkey[NPTS];   // ~bits(min d2) accumulators, 0 = identity
__device__ uint32 g_colkey[NPTS];

union F2U { ull u; float2 f; };

__device__ __forceinline__ ull pack2(float a, float b) {
    ull r; asm("mov.b64 %0, {%1, %2};" : "=l"(r) : "f"(a), "f"(b)); return r;
}
__device__ __forceinline__ ull fma2(ull a, ull b, ull c) {
    ull d; asm("fma.rn.f32x2 %0, %1, %2, %3;" : "=l"(d) : "l"(a), "l"(b), "l"(c)); return d;
}
__device__ __forceinline__ ull add2(ull a, ull b) {
    ull d; asm("add.rn.f32x2 %0, %1, %2;" : "=l"(d) : "l"(a), "l"(b)); return d;
}
__device__ __forceinline__ void redg_min_pos(uint32* addr, float v) {
    atomicMax(addr, ~__float_as_uint(v));    // no return use -> REDG.MAX
}

__global__ __launch_bounds__(THREADS, 4)
void chamfer_bidir_kernel(const float* __restrict__ pred,
                          const float* __restrict__ gt) {
    __shared__ float4 rowsm[ROWS_PB][2];   // {a0,a0,a1,a1},{a2,a2,x2,x2}

    int tid  = threadIdx.x;
    int lane = tid & 31;
    int rg   = blockIdx.x & (NROWG - 1);   // 0..255
    int cg   = blockIdx.x >> 8;            // 0..7
    int rowbase = rg * ROWS_PB;

    // ---- stage 64 pred rows into smem (duplicated for f32x2 broadcast) ----
    if (tid < ROWS_PB) {
        int r = rowbase + tid;
        float a0 = pred[3*r+0], a1 = pred[3*r+1], a2 = pred[3*r+2];
        float x2 = a0*a0 + a1*a1 + a2*a2;
        rowsm[tid][0] = make_float4(a0, a0, a1, a1);
        rowsm[tid][1] = make_float4(a2, a2, x2, x2);
    }

    // ---- 8 gt cols per thread, packed into registers ----
    ull B0[4], B1[4], B2[4], Y2[4];
    int cbase = cg * (THREADS * COLS_PT) + tid * COLS_PT;
    {
        float c[24];
        const float4* g4 = (const float4*)(gt + 3 * cbase);   // 96B aligned
        #pragma unroll
        for (int k = 0; k < 6; ++k) {
            float4 v = g4[k];
            c[4*k+0] = v.x; c[4*k+1] = v.y; c[4*k+2] = v.z; c[4*k+3] = v.w;
        }
        #pragma unroll
        for (int u = 0; u < 4; ++u) {
            float p0 = c[6*u+0], p1 = c[6*u+1], p2 = c[6*u+2];
            float q0 = c[6*u+3], q1 = c[6*u+4], q2 = c[6*u+5];
            B0[u] = pack2(-2.0f*p0, -2.0f*q0);
            B1[u] = pack2(-2.0f*p1, -2.0f*q1);
            B2[u] = pack2(-2.0f*p2, -2.0f*q2);
            Y2[u] = pack2(p0*p0 + p1*p1 + p2*p2, q0*q0 + q1*q1 + q2*q2);
        }
    }

    float cmin[COLS_PT];
    #pragma unroll
    for (int k = 0; k < COLS_PT; ++k) cmin[k] = CUDART_INF_F;

    __syncthreads();

    // ---- main loop: 32 groups of 2 interleaved rows ----
    #pragma unroll 2
    for (int g = 0; g < ROWS_PB / 2; ++g) {
        const ulonglong2* rp0 = (const ulonglong2*)&rowsm[2*g + 0][0];
        const ulonglong2* rp1 = (const ulonglong2*)&rowsm[2*g + 1][0];
        ulonglong2 ra0 = rp0[0], rb0 = rp0[1];
        ulonglong2 ra1 = rp1[0], rb1 = rp1[1];

        // dual accumulators per row: halves the serial FMNMX chain depth
        float rm0a = CUDART_INF_F, rm0b = CUDART_INF_F;
        float rm1a = CUDART_INF_F, rm1b = CUDART_INF_F;
        #pragma unroll
        for (int u = 0; u < 4; ++u) {
            F2U d0, d1;
            d0.u = add2(fma2(B0[u], ra0.x, fma2(B1[u], ra0.y, fma2(B2[u], rb0.x, Y2[u]))), rb0.y);
            d1.u = add2(fma2(B0[u], ra1.x, fma2(B1[u], ra1.y, fma2(B2[u], rb1.x, Y2[u]))), rb1.y);
            if ((u & 1) == 0) {
                rm0a = fminf(rm0a, fminf(d0.f.x, d0.f.y));
                rm1a = fminf(rm1a, fminf(d1.f.x, d1.f.y));
            } else {
                rm0b = fminf(rm0b, fminf(d0.f.x, d0.f.y));
                rm1b = fminf(rm1b, fminf(d1.f.x, d1.f.y));
            }
            cmin[2*u+0] = fminf(cmin[2*u+0], fminf(d0.f.x, d1.f.x));
            cmin[2*u+1] = fminf(cmin[2*u+1], fminf(d0.f.y, d1.f.y));
        }
        float rm0 = fminf(rm0a, rm0b);
        float rm1 = fminf(rm1a, rm1b);
        // Warp row-min: REDUX.MIN.S32 — exact for positive d2 values here.
        int i0 = __reduce_min_sync(0xFFFFFFFFu, __float_as_int(rm0));
        int i1 = __reduce_min_sync(0xFFFFFFFFu, __float_as_int(rm1));
        if (lane == 0) {
            redg_min_pos(&g_rowkey[rowbase + 2*g + 0], __int_as_float(i0));
            redg_min_pos(&g_rowkey[rowbase + 2*g + 1], __int_as_float(i1));
        }
    }

    // ---- merge col mins globally (each thread owns 8 distinct cols) ----
    #pragma unroll
    for (int k = 0; k < COLS_PT; ++k)
        redg_min_pos(&g_colkey[cbase + k], cmin[k]);
}

__global__ __launch_bounds__(1024)
void reduce_kernel(float* __restrict__ out) {
    __shared__ float ssum[1024];
    int tid = threadIdx.x;

    // Each thread: 16 rows + 16 cols, coalesced stride-1024 accesses.
    float s = 0.0f;
    #pragma unroll
    for (int k = 0; k < 16; ++k) {
        uint32 kr = g_rowkey[k * 1024 + tid];
        uint32 kc = g_colkey[k * 1024 + tid];
        s += sqrtf(fmaxf(__uint_as_float(~kr), 0.0f));
        s += sqrtf(fmaxf(__uint_as_float(~kc), 0.0f));
    }
    ssum[tid] = s;
    __syncthreads();

    // Reset keys for the next graph replay (identity = 0).
    #pragma unroll
    for (int k = 0; k < 16; ++k) {
        g_rowkey[k * 1024 + tid] = 0u;
        g_colkey[k * 1024 + tid] = 0u;
    }

    for (int st = 512; st > 0; st >>= 1) {
        if (tid < st) ssum[tid] += ssum[tid + st];
        __syncthreads();
    }
    if (tid == 0) out[0] = ssum[0] * (1.0f / 16384.0f);
}

extern "C" void kernel_launch(void* const* d_in, const int* in_sizes, int n_in,
                              void* d_out, int out_size) {
    const float* pred = (const float*)d_in[0];
    const float* gt   = (const float*)d_in[1];
    chamfer_bidir_kernel<<<NROWG * NCOLG, THREADS>>>(pred, gt);
    reduce_kernel<<<1, 1024>>>((float*)d_out);
}

// round 12
// speedup vs baseline: 1.7782x; 1.7782x over previous
#include <cuda_runtime.h>
#include <math_constants.h>

// ChamferLoss bidirectional, single pass over the 16384x16384 d2 matrix.
// d2 = (|y|^2 - 2 x.y) + |x|^2 via packed fma.rn.f32x2 (2 gt cols per op).
// Thread owns 8 gt cols in regs; pred rows broadcast from smem, 2 rows
// interleaved; row-min via REDUX.MIN.S32 (exact on positive floats).
// Grid 512 = exactly one wave at 4 blocks/SM. Partials in gmem (8 MB total),
// fused wide reduce with ticket-finalize (deterministic fixed-order sum).

#define NPTS        16384
#define NROWG       64           // row groups (256 pred rows each)
#define NCOLG       8            // col groups (2048 gt cols each)
#define ROWS_PB     256
#define COLS_PT     8
#define THREADS     256
#define NSLICE      (NCOLG * 8)  // 64 row-partial slices (per cg x warp)
#define RED_BLOCKS  128

typedef unsigned long long ull;

__device__ float g_rowpartial[NSLICE][NPTS];   // 4 MB
__device__ float g_colpartial[NROWG][NPTS];    // 4 MB
__device__ float g_bsum[RED_BLOCKS];
__device__ unsigned int g_ticket;              // zero-init; reset by last block

union F2U { ull u; float2 f; };

__device__ __forceinline__ ull pack2(float a, float b) {
    ull r; asm("mov.b64 %0, {%1, %2};" : "=l"(r) : "f"(a), "f"(b)); return r;
}
__device__ __forceinline__ ull fma2(ull a, ull b, ull c) {
    ull d; asm("fma.rn.f32x2 %0, %1, %2, %3;" : "=l"(d) : "l"(a), "l"(b), "l"(c)); return d;
}
__device__ __forceinline__ ull add2(ull a, ull b) {
    ull d; asm("add.rn.f32x2 %0, %1, %2;" : "=l"(d) : "l"(a), "l"(b)); return d;
}

__global__ __launch_bounds__(THREADS, 4)
void chamfer_bidir_kernel(const float* __restrict__ pred,
                          const float* __restrict__ gt) {
    __shared__ float4 rowsm[ROWS_PB][2];   // {a0,a0,a1,a1},{a2,a2,x2,x2}  (8 KB)

    int tid  = threadIdx.x;
    int lane = tid & 31;
    int wid  = tid >> 5;
    int rg   = blockIdx.x & (NROWG - 1);   // 0..63
    int cg   = blockIdx.x >> 6;            // 0..7
    int rowbase = rg * ROWS_PB;

    // ---- stage 256 pred rows into smem (duplicated for f32x2 broadcast) ----
    {
        int r = rowbase + tid;
        float a0 = pred[3*r+0], a1 = pred[3*r+1], a2 = pred[3*r+2];
        float x2 = a0*a0 + a1*a1 + a2*a2;
        rowsm[tid][0] = make_float4(a0, a0, a1, a1);
        rowsm[tid][1] = make_float4(a2, a2, x2, x2);
    }

    // ---- 8 gt cols per thread, packed into registers ----
    ull B0[4], B1[4], B2[4], Y2[4];
    int cbase = cg * (THREADS * COLS_PT) + tid * COLS_PT;
    {
        float c[24];
        const float4* g4 = (const float4*)(gt + 3 * cbase);   // 96B aligned
        #pragma unroll
        for (int k = 0; k < 6; ++k) {
            float4 v = g4[k];
            c[4*k+0] = v.x; c[4*k+1] = v.y; c[4*k+2] = v.z; c[4*k+3] = v.w;
        }
        #pragma unroll
        for (int u = 0; u < 4; ++u) {
            float p0 = c[6*u+0], p1 = c[6*u+1], p2 = c[6*u+2];
            float q0 = c[6*u+3], q1 = c[6*u+4], q2 = c[6*u+5];
            B0[u] = pack2(-2.0f*p0, -2.0f*q0);
            B1[u] = pack2(-2.0f*p1, -2.0f*q1);
            B2[u] = pack2(-2.0f*p2, -2.0f*q2);
            Y2[u] = pack2(p0*p0 + p1*p1 + p2*p2, q0*q0 + q1*q1 + q2*q2);
        }
    }

    float cmin[COLS_PT];
    #pragma unroll
    for (int k = 0; k < COLS_PT; ++k) cmin[k] = CUDART_INF_F;

    __syncthreads();

    float* rowout = &g_rowpartial[cg*8 + wid][rowbase];

    // ---- main loop: 128 groups of 2 interleaved rows ----
    #pragma unroll 2
    for (int g = 0; g < ROWS_PB / 2; ++g) {
        const ulonglong2* rp0 = (const ulonglong2*)&rowsm[2*g + 0][0];
        const ulonglong2* rp1 = (const ulonglong2*)&rowsm[2*g + 1][0];
        ulonglong2 ra0 = rp0[0], rb0 = rp0[1];
        ulonglong2 ra1 = rp1[0], rb1 = rp1[1];

        // dual accumulators per row: halves the serial FMNMX chain depth
        float rm0a = CUDART_INF_F, rm0b = CUDART_INF_F;
        float rm1a = CUDART_INF_F, rm1b = CUDART_INF_F;
        #pragma unroll
        for (int u = 0; u < 4; ++u) {
            F2U d0, d1;
            d0.u = add2(fma2(B0[u], ra0.x, fma2(B1[u], ra0.y, fma2(B2[u], rb0.x, Y2[u]))), rb0.y);
            d1.u = add2(fma2(B0[u], ra1.x, fma2(B1[u], ra1.y, fma2(B2[u], rb1.x, Y2[u]))), rb1.y);
            if ((u & 1) == 0) {
                rm0a = fminf(rm0a, fminf(d0.f.x, d0.f.y));
                rm1a = fminf(rm1a, fminf(d1.f.x, d1.f.y));
            } else {
                rm0b = fminf(rm0b, fminf(d0.f.x, d0.f.y));
                rm1b = fminf(rm1b, fminf(d1.f.x, d1.f.y));
            }
            cmin[2*u+0] = fminf(cmin[2*u+0], fminf(d0.f.x, d1.f.x));
            cmin[2*u+1] = fminf(cmin[2*u+1], fminf(d0.f.y, d1.f.y));
        }
        float rm0 = fminf(rm0a, rm0b);
        float rm1 = fminf(rm1a, rm1b);
        // Warp row-min: REDUX.MIN.S32 — exact for positive d2 values here.
        int i0 = __reduce_min_sync(0xFFFFFFFFu, __float_as_int(rm0));
        int i1 = __reduce_min_sync(0xFFFFFFFFu, __float_as_int(rm1));
        if (lane == 0)
            *(float2*)(rowout + 2*g) = make_float2(__int_as_float(i0), __int_as_float(i1));
    }

    // ---- write col partials (vectorized; each thread owns distinct cols) ----
    float4* cp4 = (float4*)&g_colpartial[rg][cbase];
    const float4* cm4 = (const float4*)cmin;
    cp4[0] = cm4[0];
    cp4[1] = cm4[1];
}

__global__ __launch_bounds__(256)
void reduce_kernel(float* __restrict__ out) {
    __shared__ float ssum[256];
    __shared__ unsigned int s_rank;
    int bid = blockIdx.x;   // 0..63: row side; 64..127: col side (256 elems each)
    int tid = threadIdx.x;
    float v;

    if (bid < 64) {
        int row = bid * 256 + tid;            // coalesced across threads
        float m = CUDART_INF_F;
        #pragma unroll 16
        for (int s = 0; s < NSLICE; ++s)
            m = fminf(m, g_rowpartial[s][row]);
        v = sqrtf(fmaxf(m, 0.0f));
    } else {
        int col = (bid - 64) * 256 + tid;     // coalesced across threads
        float m = CUDART_INF_F;
        #pragma unroll 16
        for (int s = 0; s < NROWG; ++s)
            m = fminf(m, g_colpartial[s][col]);
        v = sqrtf(fmaxf(m, 0.0f));
    }

    ssum[tid] = v;
    __syncthreads();
    for (int s = 128; s > 0; s >>= 1) {
        if (tid < s) ssum[tid] += ssum[tid + s];
        __syncthreads();
    }
    if (tid == 0) {
        g_bsum[bid] = ssum[0];
        __threadfence();
        s_rank = atomicAdd(&g_ticket, 1);
    }
    __syncthreads();

    // Last block to finish performs the deterministic fixed-order final sum.
    if (s_rank == RED_BLOCKS - 1 && tid == 0) {
        __threadfence();
        float s = 0.0f;
        volatile float* vb = g_bsum;
        #pragma unroll
        for (int k = 0; k < RED_BLOCKS; ++k) s += vb[k];
        out[0] = s * (1.0f / 16384.0f);
        g_ticket = 0;                       // reset for next graph replay
    }
}

extern "C" void kernel_launch(void* const* d_in, const int* in_sizes, int n_in,
                              void* d_out, int out_size) {
    const float* pred = (const float*)d_in[0];
    const float* gt   = (const float*)d_in[1];
    chamfer_bidir_kernel<<<NROWG * NCOLG, THREADS>>>(pred, gt);
    reduce_kernel<<<RED_BLOCKS, 256>>>((float*)d_out);
}

// round 16
// speedup vs baseline: 2.0877x; 1.1741x over previous
#include <cuda_runtime.h>
#include <math_constants.h>

// ChamferLoss bidirectional, single pass over the 16384x16384 d2 matrix.
// Main kernel is the R8-measured body (56.1us): minblocks 3, grid 2048,
// 8 gt cols/thread in regs, 2 pred rows interleaved from smem broadcast,
// REDUX.MIN.S32 row-min. Fused 128-block ticket reduce (deterministic).

#define NPTS        16384
#define NROWG       256          // row groups (64 pred rows each)
#define NCOLG       8            // col groups (2048 gt cols each)
#define ROWS_PB     64
#define COLS_PT     8
#define THREADS     256
#define NSLICE      (NCOLG * 8)  // 64 row-partial slices (per cg x warp)
#define RED_BLOCKS  128

typedef unsigned long long ull;

__device__ float g_rowpartial[NSLICE][NPTS];   // 4 MB
__device__ float g_colpartial[NROWG][NPTS];    // 16 MB
__device__ float g_bsum[RED_BLOCKS];
__device__ unsigned int g_ticket;              // zero-init; reset by last block

union F2U { ull u; float2 f; };

__device__ __forceinline__ ull pack2(float a, float b) {
    ull r; asm("mov.b64 %0, {%1, %2};" : "=l"(r) : "f"(a), "f"(b)); return r;
}
__device__ __forceinline__ ull fma2(ull a, ull b, ull c) {
    ull d; asm("fma.rn.f32x2 %0, %1, %2, %3;" : "=l"(d) : "l"(a), "l"(b), "l"(c)); return d;
}
__device__ __forceinline__ ull add2(ull a, ull b) {
    ull d; asm("add.rn.f32x2 %0, %1, %2;" : "=l"(d) : "l"(a), "l"(b)); return d;
}

__global__ __launch_bounds__(THREADS, 3)
void chamfer_bidir_kernel(const float* __restrict__ pred,
                          const float* __restrict__ gt) {
    __shared__ float4 rowsm[ROWS_PB][2];   // {a0,a0,a1,a1},{a2,a2,x2,x2}

    int tid  = threadIdx.x;
    int lane = tid & 31;
    int wid  = tid >> 5;
    int rg   = blockIdx.x & (NROWG - 1);   // 0..255
    int cg   = blockIdx.x >> 8;            // 0..7
    int rowbase = rg * ROWS_PB;

    // ---- stage 64 pred rows into smem (duplicated for f32x2 broadcast) ----
    if (tid < ROWS_PB) {
        int r = rowbase + tid;
        float a0 = pred[3*r+0], a1 = pred[3*r+1], a2 = pred[3*r+2];
        float x2 = a0*a0 + a1*a1 + a2*a2;
        rowsm[tid][0] = make_float4(a0, a0, a1, a1);
        rowsm[tid][1] = make_float4(a2, a2, x2, x2);
    }

    // ---- 8 gt cols per thread, packed into registers ----
    ull B0[4], B1[4], B2[4], Y2[4];
    int cbase = cg * (THREADS * COLS_PT) + tid * COLS_PT;
    {
        float c[24];
        const float4* g4 = (const float4*)(gt + 3 * cbase);   // 96B aligned
        #pragma unroll
        for (int k = 0; k < 6; ++k) {
            float4 v = g4[k];
            c[4*k+0] = v.x; c[4*k+1] = v.y; c[4*k+2] = v.z; c[4*k+3] = v.w;
        }
        #pragma unroll
        for (int u = 0; u < 4; ++u) {
            float p0 = c[6*u+0], p1 = c[6*u+1], p2 = c[6*u+2];
            float q0 = c[6*u+3], q1 = c[6*u+4], q2 = c[6*u+5];
            B0[u] = pack2(-2.0f*p0, -2.0f*q0);
            B1[u] = pack2(-2.0f*p1, -2.0f*q1);
            B2[u] = pack2(-2.0f*p2, -2.0f*q2);
            Y2[u] = pack2(p0*p0 + p1*p1 + p2*p2, q0*q0 + q1*q1 + q2*q2);
        }
    }

    float cmin[COLS_PT];
    #pragma unroll
    for (int k = 0; k < COLS_PT; ++k) cmin[k] = CUDART_INF_F;

    __syncthreads();

    float* rowout = &g_rowpartial[cg*8 + wid][rowbase];

    // ---- main loop: 32 groups of 2 interleaved rows ----
    #pragma unroll 4
    for (int g = 0; g < ROWS_PB / 2; ++g) {
        const ulonglong2* rp0 = (const ulonglong2*)&rowsm[2*g + 0][0];
        const ulonglong2* rp1 = (const ulonglong2*)&rowsm[2*g + 1][0];
        ulonglong2 ra0 = rp0[0], rb0 = rp0[1];
        ulonglong2 ra1 = rp1[0], rb1 = rp1[1];
        ull A00 = ra0.x, A01 = ra0.y, A02 = rb0.x, X20 = rb0.y;
        ull A10 = ra1.x, A11 = ra1.y, A12 = rb1.x, X21 = rb1.y;

        float rm0 = CUDART_INF_F, rm1 = CUDART_INF_F;
        #pragma unroll
        for (int u = 0; u < 4; ++u) {
            F2U d0, d1;
            d0.u = add2(fma2(B0[u], A00, fma2(B1[u], A01, fma2(B2[u], A02, Y2[u]))), X20);
            d1.u = add2(fma2(B0[u], A10, fma2(B1[u], A11, fma2(B2[u], A12, Y2[u]))), X21);
            rm0 = fminf(rm0, fminf(d0.f.x, d0.f.y));
            rm1 = fminf(rm1, fminf(d1.f.x, d1.f.y));
            cmin[2*u+0] = fminf(cmin[2*u+0], fminf(d0.f.x, d1.f.x));
            cmin[2*u+1] = fminf(cmin[2*u+1], fminf(d0.f.y, d1.f.y));
        }
        // Warp row-min: REDUX.MIN.S32 — exact for positive d2 values here.
        int i0 = __reduce_min_sync(0xFFFFFFFFu, __float_as_int(rm0));
        int i1 = __reduce_min_sync(0xFFFFFFFFu, __float_as_int(rm1));
        if (lane == 0)
            *(float2*)(rowout + 2*g) = make_float2(__int_as_float(i0), __int_as_float(i1));
    }

    // ---- write col partials (vectorized; each thread owns distinct cols) ----
    float4* cp4 = (float4*)&g_colpartial[rg][cbase];
    const float4* cm4 = (const float4*)cmin;
    cp4[0] = cm4[0];
    cp4[1] = cm4[1];
}

__global__ __launch_bounds__(256)
void reduce_kernel(float* __restrict__ out) {
    __shared__ float ssum[256];
    __shared__ unsigned int s_rank;
    int bid = blockIdx.x;   // 0..63: row side; 64..127: col side (256 elems each)
    int tid = threadIdx.x;
    float v;

    if (bid < 64) {
        int row = bid * 256 + tid;            // coalesced across threads
        float m = CUDART_INF_F;
        #pragma unroll 16
        for (int s = 0; s < NSLICE; ++s)
            m = fminf(m, g_rowpartial[s][row]);
        v = sqrtf(fmaxf(m, 0.0f));
    } else {
        int col = (bid - 64) * 256 + tid;     // coalesced across threads
        float m = CUDART_INF_F;
        #pragma unroll 16
        for (int s = 0; s < NROWG; ++s)
            m = fminf(m, g_colpartial[s][col]);
        v = sqrtf(fmaxf(m, 0.0f));
    }

    ssum[tid] = v;
    __syncthreads();
    for (int s = 128; s > 0; s >>= 1) {
        if (tid < s) ssum[tid] += ssum[tid + s];
        __syncthreads();
    }
    if (tid == 0) {
        g_bsum[bid] = ssum[0];
        __threadfence();
        s_rank = atomicAdd(&g_ticket, 1);
    }
    __syncthreads();

    // Last block to finish performs the deterministic fixed-order final sum.
    if (s_rank == RED_BLOCKS - 1 && tid == 0) {
        __threadfence();
        float s = 0.0f;
        volatile float* vb = g_bsum;
        #pragma unroll
        for (int k = 0; k < RED_BLOCKS; ++k) s += vb[k];
        out[0] = s * (1.0f / 16384.0f);
        g_ticket = 0;                       // reset for next graph replay
    }
}

extern "C" void kernel_launch(void* const* d_in, const int* in_sizes, int n_in,
                              void* d_out, int out_size) {
    const float* pred = (const float*)d_in[0];
    const float* gt   = (const float*)d_in[1];
    chamfer_bidir_kernel<<<NROWG * NCOLG, THREADS>>>(pred, gt);
    reduce_kernel<<<RED_BLOCKS, 256>>>((float*)d_out);
}